// round 8
// baseline (speedup 1.0000x reference)
#include <cuda_runtime.h>
#include <cuda_fp16.h>
#include <cstdint>

// ============================================================================
// Problem constants
// ============================================================================
#define IN_F   4096
#define OUT_F  11008
#define M_TOT  8192          // BATCH*SEQ = 4*2048

#define M_TILE 128
#define N_TILE 256
#define K_STAGE 64           // halfs per K stage (128 bytes/row, SW128 atom)
#define N_STAGES (IN_F / K_STAGE)   // 64
#define PIPE 3               // cp.async stage ring depth

// SMEM: per stage s at s*49152:
//   +0      A tile (128 rows x 64 halfs, 128B rows, SW128 swizzle)  16384 B
//   +16384  B tile (256 rows x 64 halfs, 128B rows, SW128 swizzle)  32768 B
#define SM_STAGE 49152
#define SM_A(s) ((s) * SM_STAGE)
#define SM_B(s) (SM_A(s) + 16384)
#define SMEM_BYTES (PIPE * SM_STAGE)   // 147456 (1 CTA/SM)

// fp16 scratch for converted operands (static device arrays: no allocation)
__device__ __half g_xh[(size_t)M_TOT * IN_F];   // 64 MiB
__device__ __half g_wh[(size_t)OUT_F * IN_F];   // 86 MiB

// ============================================================================
// Helpers — baseline PTX only (no tcgen05 / no 'a'-suffix features)
// ============================================================================
__device__ __forceinline__ uint32_t smem_to_u32(const void* p) {
    uint32_t a;
    asm("{ .reg .u64 t; cvta.to.shared.u64 t, %1; cvt.u32.u64 %0, t; }"
        : "=r"(a) : "l"(p));
    return a;
}

#define SMEM_SWIZZLE_128B(off) ((off) ^ (((off) >> 3) & 0x70))

#define CP_ASYNC_16(dst_u32, src_ptr) \
    asm volatile("cp.async.cg.shared.global [%0], [%1], 16;" \
                 :: "r"(dst_u32), "l"(src_ptr) : "memory")
#define CP_ASYNC_COMMIT() asm volatile("cp.async.commit_group;" ::: "memory")
#define CP_ASYNC_WAIT0()  asm volatile("cp.async.wait_group 0;" ::: "memory")
#define CP_ASYNC_WAIT1()  asm volatile("cp.async.wait_group 1;" ::: "memory")

__device__ __forceinline__ void ldsm_x4(uint32_t r[4], uint32_t addr) {
    asm volatile("ldmatrix.sync.aligned.m8n8.x4.shared.b16 {%0,%1,%2,%3}, [%4];"
                 : "=r"(r[0]), "=r"(r[1]), "=r"(r[2]), "=r"(r[3]) : "r"(addr));
}
__device__ __forceinline__ void mma16816(float c[4], const uint32_t a[4],
                                         uint32_t b0, uint32_t b1) {
    asm volatile(
        "mma.sync.aligned.m16n8k16.row.col.f32.f16.f16.f32 "
        "{%0,%1,%2,%3}, {%4,%5,%6,%7}, {%8,%9}, {%0,%1,%2,%3};"
        : "+f"(c[0]), "+f"(c[1]), "+f"(c[2]), "+f"(c[3])
        : "r"(a[0]), "r"(a[1]), "r"(a[2]), "r"(a[3]), "r"(b0), "r"(b1));
}

// ============================================================================
// Conversion kernels: fp32 x -> fp16, int32 w -> fp16 (exact for |w|<=127)
// ============================================================================
__global__ void conv_x_kernel(const float* __restrict__ in) {
    size_t i = (size_t)blockIdx.x * blockDim.x + threadIdx.x;  // one per 8 elems
    const float4* p = reinterpret_cast<const float4*>(in) + 2 * i;
    float4 a = p[0];
    float4 b = p[1];
    __half2 h0 = __floats2half2_rn(a.x, a.y);
    __half2 h1 = __floats2half2_rn(a.z, a.w);
    __half2 h2 = __floats2half2_rn(b.x, b.y);
    __half2 h3 = __floats2half2_rn(b.z, b.w);
    uint4 v;
    v.x = *reinterpret_cast<uint32_t*>(&h0);
    v.y = *reinterpret_cast<uint32_t*>(&h1);
    v.z = *reinterpret_cast<uint32_t*>(&h2);
    v.w = *reinterpret_cast<uint32_t*>(&h3);
    reinterpret_cast<uint4*>(g_xh)[i] = v;
}

__global__ void conv_w_kernel(const int* __restrict__ in) {
    size_t i = (size_t)blockIdx.x * blockDim.x + threadIdx.x;  // one per 8 elems
    const int4* p = reinterpret_cast<const int4*>(in) + 2 * i;
    int4 a = p[0];
    int4 b = p[1];
    __half2 h0 = __halves2half2(__int2half_rn(a.x), __int2half_rn(a.y));
    __half2 h1 = __halves2half2(__int2half_rn(a.z), __int2half_rn(a.w));
    __half2 h2 = __halves2half2(__int2half_rn(b.x), __int2half_rn(b.y));
    __half2 h3 = __halves2half2(__int2half_rn(b.z), __int2half_rn(b.w));
    uint4 v;
    v.x = *reinterpret_cast<uint32_t*>(&h0);
    v.y = *reinterpret_cast<uint32_t*>(&h1);
    v.z = *reinterpret_cast<uint32_t*>(&h2);
    v.w = *reinterpret_cast<uint32_t*>(&h3);
    reinterpret_cast<uint4*>(g_wh)[i] = v;
}

// ============================================================================
// GEMM: 128x256 CTA tile, 256 threads, 8 warps (2M x 4N), warp tile 64x64,
// mma.sync.m16n8k16 + ldmatrix on SW128-swizzled smem, 3-stage cp.async ring.
// ============================================================================
__device__ __forceinline__ void load_stage_async(uint32_t sbase, int s,
                                                 int m0, int n0, int kt, int tid)
{
    const __half* gA = g_xh + (size_t)m0 * IN_F + kt * K_STAGE;
    const __half* gB = g_wh + (size_t)n0 * IN_F + kt * K_STAGE;
    uint32_t sA = sbase + SM_A(s);
    uint32_t sB = sbase + SM_B(s);
    // A: 128 rows x 8 chunks of 16B -> 1024 chunks, 4 per thread
#pragma unroll
    for (int i = 0; i < 4; i++) {
        int idx = tid + i * 256;
        int r = idx >> 3, c = idx & 7;
        CP_ASYNC_16(sA + SMEM_SWIZZLE_128B(r * 128 + c * 16),
                    gA + (size_t)r * IN_F + c * 8);
    }
    // B: 256 rows x 8 chunks of 16B -> 2048 chunks, 8 per thread
#pragma unroll
    for (int i = 0; i < 8; i++) {
        int idx = tid + i * 256;
        int r = idx >> 3, c = idx & 7;
        CP_ASYNC_16(sB + SMEM_SWIZZLE_128B(r * 128 + c * 16),
                    gB + (size_t)r * IN_F + c * 8);
    }
    CP_ASYNC_COMMIT();
}

// One K=64 stage of warp-level math. Warp tile 64x64 at (wm*64, wn*64).
__device__ __forceinline__ void compute_stage(uint32_t sA, uint32_t sB,
                                              int lane, int wm, int wn,
                                              float c[4][8][4])
{
#pragma unroll
    for (int ks = 0; ks < 4; ks++) {                 // k16 steps
        uint32_t a[4][4];                            // 4 m16 tiles
        uint32_t b[4][4];                            // 4 x (n16 x k16) loads
        // A (m16 x k16 per ldsm.x4): lanes 0-7 -> rows 0-7 k+0 (mat0),
        // 8-15 -> rows 8-15 k+0 (mat1), 16-23 -> rows 0-7 +16B (mat2),
        // 24-31 -> rows 8-15 +16B (mat3): regs = mma A fragment order.
        int arow = wm * 64 + (lane & 15);
        uint32_t ak = (uint32_t)(ks * 32 + ((lane >> 4) << 4));
#pragma unroll
        for (int mi = 0; mi < 4; mi++) {
            uint32_t off = (uint32_t)(arow + mi * 16) * 128 + ak;
            ldsm_x4(a[mi], sA + SMEM_SWIZZLE_128B(off));
        }
        // B: smem holds [n][k] row-major = B^T row-major, which is exactly
        // the mma col-major B fragment under NON-trans ldmatrix: frag(t) =
        // B_nk[t/4][2*(t%4)..+1] = consecutive k for fixed n.
        // Lane->matrix mapping: mat0 = n+0..7 k+0, mat1 = n+0..7 +16B,
        // mat2 = n+8..15 k+0, mat3 = n+8..15 +16B.
        int brow = wn * 64 + ((lane >> 4) << 3) + (lane & 7);
        uint32_t bk = (uint32_t)(ks * 32 + (((lane >> 3) & 1) << 4));
#pragma unroll
        for (int g = 0; g < 4; g++) {
            uint32_t off = (uint32_t)(brow + g * 16) * 128 + bk;
            ldsm_x4(b[g], sB + SMEM_SWIZZLE_128B(off));
        }
        // 4 m16 x 8 n8 mma; ni even -> regs {0,1} (n+0..7), odd -> {2,3}
#pragma unroll
        for (int mi = 0; mi < 4; mi++) {
#pragma unroll
            for (int ni = 0; ni < 8; ni++) {
                int g = ni >> 1;
                int h = (ni & 1) << 1;
                mma16816(c[mi][ni], a[mi], b[g][h], b[g][h + 1]);
            }
        }
    }
}

__global__ void __launch_bounds__(256, 1)
gemm_hmma_kernel(const float* __restrict__ scale_p,
                 const float* __restrict__ bias,
                 float* __restrict__ out)
{
    extern __shared__ __align__(1024) char smem[];
    uint32_t sbase = smem_to_u32(smem);
    int tid  = threadIdx.x;
    int wid  = tid >> 5;
    int lane = tid & 31;
    int wm = wid & 1;          // 2 warps in M
    int wn = wid >> 1;         // 4 warps in N
    int n0 = blockIdx.x * N_TILE;
    int m0 = blockIdx.y * M_TILE;

    float c[4][8][4] = {};     // 128 fp32 accumulators

    // Prologue: 2 stages in flight
    load_stage_async(sbase, 0, m0, n0, 0, tid);
    load_stage_async(sbase, 1, m0, n0, 1, tid);

    // Mainloop. Invariant at top of iter kt: pending cp.async groups are
    // g_kt (and g_{kt+1} if it exists). wait_group 1 retires g_kt; on the
    // final iter only g_kt is pending so wait_group 0 is required.
    // WAR safety: iter kt+1 loads into buffer (kt+3)%3 == kt%3, which all
    // warps finished reading in iter kt — ordered by the __syncthreads at
    // the top of iter kt+1.
    for (int kt = 0; kt < N_STAGES; kt++) {
        if (kt + 1 < N_STAGES) { CP_ASYNC_WAIT1(); }
        else                   { CP_ASYNC_WAIT0(); }
        __syncthreads();
        int buf = kt % PIPE;
        if (kt + 2 < N_STAGES) {
            load_stage_async(sbase, (kt + 2) % PIPE, m0, n0, kt + 2, tid);
        }
        compute_stage(sbase + SM_A(buf), sbase + SM_B(buf), lane, wm, wn, c);
    }

    // Epilogue: fused scale+bias, direct float2 stores (no smem needed).
    // mma m16n8 output: d0,d1 -> row lane/4, cols (lane%4)*2,+1; d2,d3 -> row+8.
    float scale = *scale_p;
    int r0    = m0 + wm * 64 + (lane >> 2);
    int cbase = n0 + wn * 64 + (lane & 3) * 2;
#pragma unroll
    for (int mi = 0; mi < 4; mi++) {
        int row = r0 + mi * 16;
#pragma unroll
        for (int ni = 0; ni < 8; ni++) {
            int col = cbase + ni * 8;
            float b0 = __ldg(bias + col);
            float b1 = __ldg(bias + col + 1);
            float2 v;
            v.x = c[mi][ni][0] * scale + b0;
            v.y = c[mi][ni][1] * scale + b1;
            *reinterpret_cast<float2*>(out + (size_t)row * OUT_F + col) = v;
            v.x = c[mi][ni][2] * scale + b0;
            v.y = c[mi][ni][3] * scale + b1;
            *reinterpret_cast<float2*>(out + (size_t)(row + 8) * OUT_F + col) = v;
        }
    }
}

// ============================================================================
// Launch
// ============================================================================
extern "C" void kernel_launch(void* const* d_in, const int* in_sizes, int n_in,
                              void* d_out, int out_size)
{
    const float* x     = (const float*)d_in[0];   // [4, 2048, 4096] fp32
    const int*   w     = (const int*)d_in[1];     // [11008, 4096] int32
    const float* scale = (const float*)d_in[2];   // scalar
    const float* bias  = (const float*)d_in[3];   // [11008]
    float*       out   = (float*)d_out;           // [4, 2048, 11008] fp32

    // Conversions: one thread per 8 elements, exact division
    conv_x_kernel<<<(M_TOT * (size_t)IN_F) / 8 / 256, 256>>>(x);
    conv_w_kernel<<<((size_t)OUT_F * IN_F) / 8 / 256, 256>>>(w);

    cudaFuncSetAttribute(gemm_hmma_kernel,
                         cudaFuncAttributeMaxDynamicSharedMemorySize, SMEM_BYTES);
    dim3 grid(OUT_F / N_TILE, M_TOT / M_TILE);   // (43, 64)
    gemm_hmma_kernel<<<grid, 256, SMEM_BYTES>>>(scale, bias, out);
}

// round 10
// speedup vs baseline: 1.1877x; 1.1877x over previous
#include <cuda_runtime.h>
#include <cuda_fp16.h>
#include <cstdint>

// ============================================================================
// Problem constants
// ============================================================================
#define IN_F   4096
#define OUT_F  11008
#define M_TOT  8192          // BATCH*SEQ = 4*2048

#define M_TILE 128
#define N_TILE 256
#define K_STAGE 64           // halfs per K stage (128 bytes/row, SW128 atom)
#define N_STAGES (IN_F / K_STAGE)   // 64
#define PIPE 4               // cp.async stage ring depth (64 % 4 == 0)

// SMEM: per stage s at s*49152:
//   +0      A tile (128 rows x 64 halfs, 128B rows, SW128 swizzle)  16384 B
//   +16384  B tile (256 rows x 64 halfs, 128B rows, SW128 swizzle)  32768 B
#define SM_STAGE 49152
#define SM_A(s) ((s) * SM_STAGE)
#define SM_B(s) (SM_A(s) + 16384)
#define SMEM_BYTES (PIPE * SM_STAGE)   // 196608 (1 CTA/SM)

// fp16 scratch for converted operands (static device arrays: no allocation)
__device__ __half g_xh[(size_t)M_TOT * IN_F];   // 64 MiB
__device__ __half g_wh[(size_t)OUT_F * IN_F];   // 86 MiB

// ============================================================================
// Helpers — baseline PTX only
// ============================================================================
__device__ __forceinline__ uint32_t smem_to_u32(const void* p) {
    uint32_t a;
    asm("{ .reg .u64 t; cvta.to.shared.u64 t, %1; cvt.u32.u64 %0, t; }"
        : "=r"(a) : "l"(p));
    return a;
}

#define SMEM_SWIZZLE_128B(off) ((off) ^ (((off) >> 3) & 0x70))

#define CP_ASYNC_16(dst_u32, src_ptr) \
    asm volatile("cp.async.cg.shared.global [%0], [%1], 16;" \
                 :: "r"(dst_u32), "l"(src_ptr) : "memory")
#define CP_ASYNC_COMMIT() asm volatile("cp.async.commit_group;" ::: "memory")
#define CP_ASYNC_WAIT(n)  asm volatile("cp.async.wait_group %0;" :: "n"(n) : "memory")

__device__ __forceinline__ void ldsm_x4(uint32_t r[4], uint32_t addr) {
    asm volatile("ldmatrix.sync.aligned.m8n8.x4.shared.b16 {%0,%1,%2,%3}, [%4];"
                 : "=r"(r[0]), "=r"(r[1]), "=r"(r[2]), "=r"(r[3]) : "r"(addr));
}
__device__ __forceinline__ void mma16816(float c[4], const uint32_t a[4],
                                         uint32_t b0, uint32_t b1) {
    asm volatile(
        "mma.sync.aligned.m16n8k16.row.col.f32.f16.f16.f32 "
        "{%0,%1,%2,%3}, {%4,%5,%6,%7}, {%8,%9}, {%0,%1,%2,%3};"
        : "+f"(c[0]), "+f"(c[1]), "+f"(c[2]), "+f"(c[3])
        : "r"(a[0]), "r"(a[1]), "r"(a[2]), "r"(a[3]), "r"(b0), "r"(b1));
}

// ============================================================================
// Conversion kernels: fp32 x -> fp16, int32 w -> fp16 (exact for |w|<=127)
// ============================================================================
__global__ void conv_x_kernel(const float* __restrict__ in) {
    size_t i = (size_t)blockIdx.x * blockDim.x + threadIdx.x;  // one per 8 elems
    const float4* p = reinterpret_cast<const float4*>(in) + 2 * i;
    float4 a = p[0];
    float4 b = p[1];
    __half2 h0 = __floats2half2_rn(a.x, a.y);
    __half2 h1 = __floats2half2_rn(a.z, a.w);
    __half2 h2 = __floats2half2_rn(b.x, b.y);
    __half2 h3 = __floats2half2_rn(b.z, b.w);
    uint4 v;
    v.x = *reinterpret_cast<uint32_t*>(&h0);
    v.y = *reinterpret_cast<uint32_t*>(&h1);
    v.z = *reinterpret_cast<uint32_t*>(&h2);
    v.w = *reinterpret_cast<uint32_t*>(&h3);
    reinterpret_cast<uint4*>(g_xh)[i] = v;
}

__global__ void conv_w_kernel(const int* __restrict__ in) {
    size_t i = (size_t)blockIdx.x * blockDim.x + threadIdx.x;  // one per 8 elems
    const int4* p = reinterpret_cast<const int4*>(in) + 2 * i;
    int4 a = p[0];
    int4 b = p[1];
    __half2 h0 = __halves2half2(__int2half_rn(a.x), __int2half_rn(a.y));
    __half2 h1 = __halves2half2(__int2half_rn(a.z), __int2half_rn(a.w));
    __half2 h2 = __halves2half2(__int2half_rn(b.x), __int2half_rn(b.y));
    __half2 h3 = __halves2half2(__int2half_rn(b.z), __int2half_rn(b.w));
    uint4 v;
    v.x = *reinterpret_cast<uint32_t*>(&h0);
    v.y = *reinterpret_cast<uint32_t*>(&h1);
    v.z = *reinterpret_cast<uint32_t*>(&h2);
    v.w = *reinterpret_cast<uint32_t*>(&h3);
    reinterpret_cast<uint4*>(g_wh)[i] = v;
}

// ============================================================================
// GEMM: 128x256 CTA tile, 256 threads, 8 warps (2M x 4N), warp tile 64x64,
// mma.sync.m16n8k16 + ldmatrix on SW128-swizzled smem, 4-stage cp.async ring.
// ============================================================================
struct Frags { uint32_t a[4][4]; uint32_t b[4][4]; };

// ldmatrix one k16 step into f. Layout identical to the verified R7 kernel.
__device__ __forceinline__ void load_frags(Frags& f, uint32_t sA, uint32_t sB,
                                           int ks, int lane, int wm, int wn)
{
    int arow = wm * 64 + (lane & 15);
    uint32_t ak = (uint32_t)(ks * 32 + ((lane >> 4) << 4));
#pragma unroll
    for (int mi = 0; mi < 4; mi++) {
        uint32_t off = (uint32_t)(arow + mi * 16) * 128 + ak;
        ldsm_x4(f.a[mi], sA + SMEM_SWIZZLE_128B(off));
    }
    int brow = wn * 64 + ((lane >> 4) << 3) + (lane & 7);
    uint32_t bk = (uint32_t)(ks * 32 + (((lane >> 3) & 1) << 4));
#pragma unroll
    for (int g = 0; g < 4; g++) {
        uint32_t off = (uint32_t)(brow + g * 16) * 128 + bk;
        ldsm_x4(f.b[g], sB + SMEM_SWIZZLE_128B(off));
    }
}

__device__ __forceinline__ void mma_frags(const Frags& f, float c[4][8][4])
{
#pragma unroll
    for (int mi = 0; mi < 4; mi++) {
#pragma unroll
        for (int ni = 0; ni < 8; ni++) {
            int g = ni >> 1;
            int h = (ni & 1) << 1;
            mma16816(c[mi][ni], f.a[mi], f.b[g][h], f.b[g][h + 1]);
        }
    }
}

// One K=64 stage, ks-software-pipelined: ldsm for ks+1 overlaps mma of ks.
__device__ __forceinline__ void compute_stage(uint32_t sA, uint32_t sB,
                                              int lane, int wm, int wn,
                                              float c[4][8][4])
{
    Frags f0, f1;
    load_frags(f0, sA, sB, 0, lane, wm, wn);
    load_frags(f1, sA, sB, 1, lane, wm, wn);
    mma_frags(f0, c);
    load_frags(f0, sA, sB, 2, lane, wm, wn);
    mma_frags(f1, c);
    load_frags(f1, sA, sB, 3, lane, wm, wn);
    mma_frags(f0, c);
    mma_frags(f1, c);
}

__global__ void __launch_bounds__(256, 1)
gemm_hmma_kernel(const float* __restrict__ scale_p,
                 const float* __restrict__ bias,
                 float* __restrict__ out)
{
    extern __shared__ __align__(1024) char smem[];
    uint32_t sbase = smem_to_u32(smem);
    int tid  = threadIdx.x;
    int wid  = tid >> 5;
    int lane = tid & 31;
    int wm = wid & 1;          // 2 warps in M
    int wn = wid >> 1;         // 4 warps in N
    int n0 = blockIdx.x * N_TILE;
    int m0 = blockIdx.y * M_TILE;

    // cp.async geometry, affine-collapsed (addresses identical to R7/R8):
    //   chunk i: row r = (tid>>3) + 32*i, col c = tid&7 (const) ->
    //   src_i = base + i*32*IN_F (halfs); dst_i = d0 + i*4096 (the +32-row
    //   step only touches offset bits >=12, and the SW128 XOR term depends
    //   on bits 7-9 = (r mod 32)*128, invariant across i).
    int r0c = tid >> 3;
    int cc  = tid & 7;
    const __half* pA = g_xh + (size_t)(m0 + r0c) * IN_F + cc * 8;
    const __half* pB = g_wh + (size_t)(n0 + r0c) * IN_F + cc * 8;
    uint32_t d0 = SMEM_SWIZZLE_128B((uint32_t)(r0c * 128 + cc * 16));

    float c[4][8][4] = {};     // 128 fp32 accumulators

#define ISSUE_STAGE(bufc, kt_) do { \
        const __half* _a = pA + (kt_) * K_STAGE; \
        const __half* _b = pB + (kt_) * K_STAGE; \
        uint32_t _sA = sbase + SM_A(bufc) + d0; \
        uint32_t _sB = sbase + SM_B(bufc) + d0; \
        CP_ASYNC_16(_sA + 0 * 4096, _a + (size_t)0 * 32 * IN_F); \
        CP_ASYNC_16(_sA + 1 * 4096, _a + (size_t)1 * 32 * IN_F); \
        CP_ASYNC_16(_sA + 2 * 4096, _a + (size_t)2 * 32 * IN_F); \
        CP_ASYNC_16(_sA + 3 * 4096, _a + (size_t)3 * 32 * IN_F); \
        CP_ASYNC_16(_sB + 0 * 4096, _b + (size_t)0 * 32 * IN_F); \
        CP_ASYNC_16(_sB + 1 * 4096, _b + (size_t)1 * 32 * IN_F); \
        CP_ASYNC_16(_sB + 2 * 4096, _b + (size_t)2 * 32 * IN_F); \
        CP_ASYNC_16(_sB + 3 * 4096, _b + (size_t)3 * 32 * IN_F); \
        CP_ASYNC_16(_sB + 4 * 4096, _b + (size_t)4 * 32 * IN_F); \
        CP_ASYNC_16(_sB + 5 * 4096, _b + (size_t)5 * 32 * IN_F); \
        CP_ASYNC_16(_sB + 6 * 4096, _b + (size_t)6 * 32 * IN_F); \
        CP_ASYNC_16(_sB + 7 * 4096, _b + (size_t)7 * 32 * IN_F); \
        CP_ASYNC_COMMIT(); \
    } while (0)

    // Prologue: 3 stages in flight (g0, g1, g2)
    ISSUE_STAGE(0, 0);
    ISSUE_STAGE(1, 1);
    ISSUE_STAGE(2, 2);

    // Steady state, unrolled by PIPE=4 so buffer indices are compile-time.
    // Invariant at top of iter kt: pending groups {g_kt, g_kt+1, g_kt+2};
    // wait_group 2 retires g_kt. Iter kt issues g_{kt+3} into buffer
    // (kt+3)%4 == (kt-1)%4, consumed in iter kt-1 and ordered by the
    // __syncthreads at the top of this iter.
#define STEP(bufc, kt_, WAITN, DO_ISSUE) do { \
        CP_ASYNC_WAIT(WAITN); \
        __syncthreads(); \
        if (DO_ISSUE) { ISSUE_STAGE(((bufc) + 3) & 3, (kt_) + 3); } \
        compute_stage(sbase + SM_A(bufc), sbase + SM_B(bufc), lane, wm, wn, c); \
    } while (0)

#pragma unroll 1
    for (int q = 0; q < 15; q++) {     // kt = 4q .. 4q+3, kt <= 59
        int kt = q * 4;
        STEP(0, kt + 0, 2, true);
        STEP(1, kt + 1, 2, true);
        STEP(2, kt + 2, 2, true);
        STEP(3, kt + 3, 2, true);
    }
    // Tail: kt = 60 (issues g63), 61, 62, 63. Pending at top:
    // 60:{60,61,62} w2; 61:{61,62,63} w2; 62:{62,63} w1; 63:{63} w0.
    STEP(0, 60, 2, true);
    STEP(1, 61, 2, false);
    STEP(2, 62, 1, false);
    STEP(3, 63, 0, false);
#undef STEP
#undef ISSUE_STAGE

    // Epilogue: fused scale+bias, direct float2 stores.
    // mma m16n8 output: d0,d1 -> row lane/4, cols (lane%4)*2,+1; d2,d3 -> row+8.
    float scale = *scale_p;
    int rr0   = m0 + wm * 64 + (lane >> 2);
    int cbase = n0 + wn * 64 + (lane & 3) * 2;
#pragma unroll
    for (int mi = 0; mi < 4; mi++) {
        int row = rr0 + mi * 16;
#pragma unroll
        for (int ni = 0; ni < 8; ni++) {
            int col = cbase + ni * 8;
            float b0 = __ldg(bias + col);
            float b1 = __ldg(bias + col + 1);
            float2 v;
            v.x = c[mi][ni][0] * scale + b0;
            v.y = c[mi][ni][1] * scale + b1;
            *reinterpret_cast<float2*>(out + (size_t)row * OUT_F + col) = v;
            v.x = c[mi][ni][2] * scale + b0;
            v.y = c[mi][ni][3] * scale + b1;
            *reinterpret_cast<float2*>(out + (size_t)(row + 8) * OUT_F + col) = v;
        }
    }
}

// ============================================================================
// Launch
// ============================================================================
extern "C" void kernel_launch(void* const* d_in, const int* in_sizes, int n_in,
                              void* d_out, int out_size)
{
    const float* x     = (const float*)d_in[0];   // [4, 2048, 4096] fp32
    const int*   w     = (const int*)d_in[1];     // [11008, 4096] int32
    const float* scale = (const float*)d_in[2];   // scalar
    const float* bias  = (const float*)d_in[3];   // [11008]
    float*       out   = (float*)d_out;           // [4, 2048, 11008] fp32

    // Conversions: one thread per 8 elements, exact division
    conv_x_kernel<<<(M_TOT * (size_t)IN_F) / 8 / 256, 256>>>(x);
    conv_w_kernel<<<((size_t)OUT_F * IN_F) / 8 / 256, 256>>>(w);

    cudaFuncSetAttribute(gemm_hmma_kernel,
                         cudaFuncAttributeMaxDynamicSharedMemorySize, SMEM_BYTES);
    dim3 grid(OUT_F / N_TILE, M_TOT / M_TILE);   // (43, 64)
    gemm_hmma_kernel<<<grid, 256, SMEM_BYTES>>>(scale, bias, out);
}